// round 3
// baseline (speedup 1.0000x reference)
#include <cuda_runtime.h>
#include <cstdint>

// Fused ConvTranspose3d(32->64,k5,s2,p2) + MaxPool2 + MaxPool3 + channel-sum.
// The two stride-matched pools compose into one 6x6x6 stride-6 max over the conv
// output (positions 0..29 / 0..59 / 0..59); bias is per-channel so it folds in
// after the max.
//
// CTA = (n, d2, h2). Warp = w2 window (10 warps). Lane = cout pair
// (64 couts = 32 f32x2 pairs; fma.rn.f32x2 -> 2 MACs/inst).
// Input patch cin x 5 x 5 x 32, stored DUPLICATED as f32x2 (200 KB smem) so the
// x-broadcast is a single LDS.64. Weights are pre-paired by a prepass kernel into
// g_wp and read directly from L2 with coalesced per-lane LDG.64 (no smem staging,
// no per-chunk barriers).

#define CIN 32
#define COUT 64
#define DI 16
#define HI 32
#define WI 32
#define NTH 320
#define XS_ELEMS 25600               // 32cin * 5ad * 5ah * 32slots
#define SMEM_BYTES (XS_ELEMS * 8)    // duplicated f32x2 -> 200 KB

typedef unsigned long long u64;

__device__ u64 g_wp[CIN * 125 * 32];   // [(cin*125 + kd*25 + kh*5 + kw)*32 + lane]
                                       // low32 = w[cin][2*lane][tap], high32 = w[cin][2*lane+1][tap]

__global__ void prep_kernel(const float* __restrict__ w) {
    int idx = blockIdx.x * blockDim.x + threadIdx.x;
    if (idx >= CIN * 125 * 32) return;
    int lane = idx & 31;
    int t = idx >> 5;
    int cin = t / 125, tap = t % 125;
    unsigned int a = __float_as_uint(w[(cin * COUT + 2 * lane) * 125 + tap]);
    unsigned int b = __float_as_uint(w[(cin * COUT + 2 * lane + 1) * 125 + tap]);
    g_wp[idx] = ((u64)b << 32) | (u64)a;
}

__device__ __forceinline__ u64 ffma2(u64 a, u64 b, u64 c) {
    u64 d;
    asm("fma.rn.f32x2 %0, %1, %2, %3;" : "=l"(d) : "l"(a), "l"(b), "l"(c));
    return d;
}
__device__ __forceinline__ void unpack2(u64 v, float& lo, float& hi) {
    asm("mov.b64 {%0, %1}, %2;" : "=f"(lo), "=f"(hi) : "l"(v));
}

// Accumulate all conv contributions for one oh-plane (6 od x 6 ow window slice)
// for this thread's cout pair. xs layout (u64): ((cin*5+ad)*5+ah)*32 + slot,
// slot = iw + 1, both f32 halves equal.
template <int NKH>
__device__ __forceinline__ void accum_body(u64 acc[36],
                                           const u64* __restrict__ xsu,
                                           int oh, int par, int w2, int lane) {
#pragma unroll 1
    for (int cin = 0; cin < CIN; cin++) {
#pragma unroll 1
        for (int khi = 0; khi < NKH; khi++) {
            int kh = par + 2 * khi;
            int ah = ((oh + 2 - kh) >> 1) + 1;          // in [0,4]

            // 25 coalesced LDG.64 from L2-resident prepared weights
            const u64* wb = g_wp + (cin * 125 + kh * 5) * 32 + lane;
            u64 wreg[5][5];
#pragma unroll
            for (int kd = 0; kd < 5; kd++)
#pragma unroll
                for (int kw = 0; kw < 5; kw++)
                    wreg[kd][kw] = __ldg(wb + (kd * 25 + kw) * 32);

            const u64* xb = xsu + ((cin * 5) * 5 + ah) * 32 + 3 * w2;
#pragma unroll
            for (int a = 0; a < 5; a++) {
                u64 xp[5];
#pragma unroll
                for (int j = 0; j < 5; j++) xp[j] = xb[a * 160 + j];  // LDS.64 broadcast
#pragma unroll
                for (int kd = 0; kd < 5; kd++) {
                    int odl = 2 * a + kd - 4;            // compile-time after unroll
                    if (odl < 0 || odl > 5) continue;
#pragma unroll
                    for (int kw = 0; kw < 5; kw++) {
                        int p = kw & 1;
                        int jb = 2 - (kw >> 1);
#pragma unroll
                        for (int t3 = 0; t3 < 3; t3++) {
                            int ow = p + 2 * t3;
                            acc[odl * 6 + ow] =
                                ffma2(wreg[kd][kw], xp[jb + t3], acc[odl * 6 + ow]);
                        }
                    }
                }
            }
        }
    }
}

extern __shared__ u64 smem_dyn[];

__global__ void __launch_bounds__(NTH, 1)
fused_kernel(const float* __restrict__ x, const float* __restrict__ bias,
             float* __restrict__ out) {
    u64* xsu = smem_dyn;

    int blk = blockIdx.x;
    int h2 = blk % 10;
    int d2 = (blk / 10) % 5;
    int n = blk / 50;
    int tid = threadIdx.x;

    // ---- load input patch: cin x (id0..id0+4) x (ih0..ih0+4) x (iw=-1..30) ----
    int id0 = 3 * d2 - 1, ih0 = 3 * h2 - 1;
    const float* xbase = x + (size_t)n * CIN * DI * HI * WI;
    for (int i = tid; i < XS_ELEMS; i += NTH) {
        int slot = i & 31;               // iw + 1
        int ah = (i >> 5) % 5;
        int rest = i / 160;
        int ad = rest % 5;
        int cin = rest / 5;
        int iw = slot - 1, id = id0 + ad, ih = ih0 + ah;
        float v = 0.f;
        if (iw >= 0 && id >= 0 && ih >= 0)   // upper bounds always in range for used windows
            v = xbase[((cin * DI + id) * HI + ih) * WI + iw];
        unsigned int u = __float_as_uint(v);
        xsu[i] = ((u64)u << 32) | (u64)u;    // duplicate into both f32x2 halves
    }
    __syncthreads();

    int w2 = tid >> 5;                   // warp id = output w2
    int lane = tid & 31;                 // cout pair (2*lane, 2*lane+1)
    float b0 = bias[2 * lane], b1 = bias[2 * lane + 1];
    float m0 = -3.4e38f, m1 = -3.4e38f;

#pragma unroll 1
    for (int oh = 0; oh < 6; oh++) {
        int par = oh & 1;
        u64 acc[36];
#pragma unroll
        for (int i = 0; i < 36; i++) acc[i] = 0ull;

        if (par) accum_body<2>(acc, xsu, oh, par, w2, lane);
        else     accum_body<3>(acc, xsu, oh, par, w2, lane);

        // fold this oh-plane (6 od x 6 ow) into the running per-channel max
#pragma unroll
        for (int i = 0; i < 36; i++) {
            float lo, hi;
            unpack2(acc[i], lo, hi);
            m0 = fmaxf(m0, lo);
            m1 = fmaxf(m1, hi);
        }
    }

    float s = (m0 + b0) + (m1 + b1);     // bias folded after max; sum lane's 2 couts
#pragma unroll
    for (int off = 16; off; off >>= 1) s += __shfl_xor_sync(0xffffffffu, s, off);
    if (lane == 0) out[((n * 5 + d2) * 10 + h2) * 10 + w2] = s;
}

extern "C" void kernel_launch(void* const* d_in, const int* in_sizes, int n_in,
                              void* d_out, int out_size) {
    const float* x = (const float*)d_in[0];
    const float* w = (const float*)d_in[1];
    const float* b = (const float*)d_in[2];
    float* out = (float*)d_out;

    static int configured = 0;
    if (!configured) {
        cudaFuncSetAttribute(fused_kernel, cudaFuncAttributeMaxDynamicSharedMemorySize,
                             SMEM_BYTES);
        configured = 1;
    }

    prep_kernel<<<(CIN * 125 * 32 + 255) / 256, 256>>>(w);
    fused_kernel<<<16 * 5 * 10, NTH, SMEM_BYTES>>>(x, b, out);
}

// round 4
// speedup vs baseline: 1.0570x; 1.0570x over previous
#include <cuda_runtime.h>
#include <cstdint>

// Fused ConvTranspose3d(32->64,k5,s2,p2) + MaxPool2 + MaxPool3 + channel-sum.
// Pools compose into a 6x6x6 stride-6 max over conv output; bias folds after max.
//
// CTA = (n, d2, h2), 640 threads = 20 warps.
// warp = (w2 in 0..9) x (od-half ODH in {0,1}); lane = cout pair (f32x2).
// Input patch cin x 5 x 5 x 32 stored DUPLICATED as f32x2 (200 KB smem) -> x
// broadcast is one LDS.64. Weights pre-paired (g_wp) and read as coalesced
// per-lane LDG.64 (L1-shared across all 20 warps). acc = 18 u64 (3 od x 6 ow)
// so 640 threads fit the register file.

#define CIN 32
#define COUT 64
#define DI 16
#define HI 32
#define WI 32
#define NTH 640
#define XS_ELEMS 25600               // 32cin * 5ad * 5ah * 32slots
#define SMEM_BYTES (XS_ELEMS * 8)    // duplicated f32x2 -> 200 KB

typedef unsigned long long u64;

__device__ u64 g_wp[CIN * 125 * 32];   // [(cin*125 + kd*25 + kh*5 + kw)*32 + lane]
                                       // lo = w[cin][2*lane][tap], hi = w[cin][2*lane+1][tap]

__global__ void prep_kernel(const float* __restrict__ w) {
    int idx = blockIdx.x * blockDim.x + threadIdx.x;
    if (idx >= CIN * 125 * 32) return;
    int lane = idx & 31;
    int t = idx >> 5;
    int cin = t / 125, tap = t % 125;
    unsigned int a = __float_as_uint(w[(cin * COUT + 2 * lane) * 125 + tap]);
    unsigned int b = __float_as_uint(w[(cin * COUT + 2 * lane + 1) * 125 + tap]);
    g_wp[idx] = ((u64)b << 32) | (u64)a;
}

__device__ __forceinline__ u64 ffma2(u64 a, u64 b, u64 c) {
    u64 d;
    asm("fma.rn.f32x2 %0, %1, %2, %3;" : "=l"(d) : "l"(a), "l"(b), "l"(c));
    return d;
}
__device__ __forceinline__ void unpack2(u64 v, float& lo, float& hi) {
    asm("mov.b64 {%0, %1}, %2;" : "=f"(lo), "=f"(hi) : "l"(v));
}

// Accumulate this od-half's slice of one oh-plane for this thread's cout pair.
// xs layout (u64): ((cin*5+ad)*5+ah)*32 + slot, slot = iw+1, halves duplicated.
template <int NKH, int ODH>
__device__ __forceinline__ void accum_body(u64 acc[18],
                                           const u64* __restrict__ xsu,
                                           int oh, int par, int w2, int lane) {
#pragma unroll 1
    for (int cin = 0; cin < CIN; cin++) {
#pragma unroll 1
        for (int khi = 0; khi < NKH; khi++) {
            int kh = par + 2 * khi;
            int ah = ((oh + 2 - kh) >> 1) + 1;          // in [0,4]
            const u64* wbase = g_wp + (cin * 125 + kh * 5) * 32 + lane;
            const u64* xb = xsu + (cin * 25 + ah) * 32 + 3 * w2;
#pragma unroll
            for (int a = 0; a < 5; a++) {
                u64 xp[5];
                bool loaded = false;
#pragma unroll
                for (int kd = 0; kd < 5; kd++) {
                    int odl = 2 * a + kd - 4;            // compile-time after unroll
                    if (odl < 3 * ODH || odl > 3 * ODH + 2) continue;
                    if (!loaded) {
#pragma unroll
                        for (int j = 0; j < 5; j++) xp[j] = xb[a * 160 + j];
                        loaded = true;
                    }
                    u64 wrow[5];
#pragma unroll
                    for (int kw = 0; kw < 5; kw++)
                        wrow[kw] = __ldg(wbase + (kd * 25 + kw) * 32);
                    int ol = odl - 3 * ODH;              // 0..2
#pragma unroll
                    for (int kw = 0; kw < 5; kw++) {
                        int p = kw & 1;
                        int jb = 2 - (kw >> 1);
#pragma unroll
                        for (int t3 = 0; t3 < 3; t3++) {
                            int ow = p + 2 * t3;
                            acc[ol * 6 + ow] =
                                ffma2(wrow[kw], xp[jb + t3], acc[ol * 6 + ow]);
                        }
                    }
                }
            }
        }
    }
}

extern __shared__ u64 smem_dyn[];

__global__ void __launch_bounds__(NTH, 1)
fused_kernel(const float* __restrict__ x, const float* __restrict__ bias,
             float* __restrict__ out) {
    u64* xsu = smem_dyn;

    int blk = blockIdx.x;
    int h2 = blk % 10;
    int d2 = (blk / 10) % 5;
    int n = blk / 50;
    int tid = threadIdx.x;

    // ---- load input patch: cin x (id0..id0+4) x (ih0..ih0+4) x (iw=-1..30) ----
    int id0 = 3 * d2 - 1, ih0 = 3 * h2 - 1;
    const float* xbase = x + (size_t)n * CIN * DI * HI * WI;
    for (int i = tid; i < XS_ELEMS; i += NTH) {
        int slot = i & 31;               // iw + 1
        int ah = (i >> 5) % 5;
        int rest = i / 160;
        int ad = rest % 5;
        int cin = rest / 5;
        int iw = slot - 1, id = id0 + ad, ih = ih0 + ah;
        float v = 0.f;
        if (iw >= 0 && id >= 0 && ih >= 0)   // upper bounds always in range for used windows
            v = xbase[((cin * DI + id) * HI + ih) * WI + iw];
        unsigned int u = __float_as_uint(v);
        xsu[i] = ((u64)u << 32) | (u64)u;    // duplicate into both f32x2 halves
    }
    __syncthreads();

    int wid = tid >> 5;
    int w2 = wid % 10;                   // output w2 window
    int odh = wid / 10;                  // od half: 0 -> od 0..2, 1 -> od 3..5
    int lane = tid & 31;                 // cout pair (2*lane, 2*lane+1)
    float m0 = -3.4e38f, m1 = -3.4e38f;

#pragma unroll 1
    for (int oh = 0; oh < 6; oh++) {
        int par = oh & 1;
        u64 acc[18];
#pragma unroll
        for (int i = 0; i < 18; i++) acc[i] = 0ull;

        if (odh == 0) {
            if (par) accum_body<2, 0>(acc, xsu, oh, par, w2, lane);
            else     accum_body<3, 0>(acc, xsu, oh, par, w2, lane);
        } else {
            if (par) accum_body<2, 1>(acc, xsu, oh, par, w2, lane);
            else     accum_body<3, 1>(acc, xsu, oh, par, w2, lane);
        }

        // fold this oh-plane slice (3 od x 6 ow) into the running per-channel max
#pragma unroll
        for (int i = 0; i < 18; i++) {
            float lo, hi;
            unpack2(acc[i], lo, hi);
            m0 = fmaxf(m0, lo);
            m1 = fmaxf(m1, hi);
        }
    }

    // ---- merge od halves (patch no longer needed -> reuse smem), bias, sum ----
    __syncthreads();
    float* red = (float*)smem_dyn;
    if (odh == 1) {
        red[(w2 * 32 + lane) * 2 + 0] = m0;
        red[(w2 * 32 + lane) * 2 + 1] = m1;
    }
    __syncthreads();
    if (odh == 0) {
        m0 = fmaxf(m0, red[(w2 * 32 + lane) * 2 + 0]);
        m1 = fmaxf(m1, red[(w2 * 32 + lane) * 2 + 1]);
        float b0 = bias[2 * lane], b1 = bias[2 * lane + 1];
        float s = (m0 + b0) + (m1 + b1);     // bias after max; sum lane's 2 couts
#pragma unroll
        for (int off = 16; off; off >>= 1) s += __shfl_xor_sync(0xffffffffu, s, off);
        if (lane == 0) out[((n * 5 + d2) * 10 + h2) * 10 + w2] = s;
    }
}

extern "C" void kernel_launch(void* const* d_in, const int* in_sizes, int n_in,
                              void* d_out, int out_size) {
    const float* x = (const float*)d_in[0];
    const float* w = (const float*)d_in[1];
    const float* b = (const float*)d_in[2];
    float* out = (float*)d_out;

    static int configured = 0;
    if (!configured) {
        cudaFuncSetAttribute(fused_kernel, cudaFuncAttributeMaxDynamicSharedMemorySize,
                             SMEM_BYTES);
        configured = 1;
    }

    prep_kernel<<<(CIN * 125 * 32 + 255) / 256, 256>>>(w);
    fused_kernel<<<16 * 5 * 10, NTH, SMEM_BYTES>>>(x, b, out);
}